// round 13
// baseline (speedup 1.0000x reference)
#include <cuda_runtime.h>
#include <cstdint>

#define NN 50000
#define E_RAW 1600000
#define E_TOT (E_RAW + NN)
#define F_IN 512
#define H1N 8
#define C1N 8
#define F1 64
#define C2 40
#define NB_SCAN ((NN + 255) / 256)
#define BM 128
#define BK 32

// ---------------- scratch (static __device__ — no allocation) ----------------
__device__ int   g_src[E_TOT];
__device__ int   g_dstv[E_TOT];
__device__ int   g_csr_src[E_TOT];
__device__ int   g_deg[NN];
__device__ int   g_off[NN + 1];
__device__ int   g_cur[NN];
__device__ int   g_bsum[NB_SCAN];
__device__ int   g_boff[NB_SCAN];
__device__ int   g_is64;
__device__ __align__(16) float g_W1h[F_IN * F1];
__device__ __align__(16) float g_W1l[F_IN * F1];
__device__ __align__(16) float g_h1[(size_t)NN * F1];
__device__ __align__(16) float g_x1[(size_t)NN * F1];
__device__ __align__(16) float g_as1[(size_t)NN * H1N];
__device__ __align__(16) float g_ad1[(size_t)NN * H1N];
__device__ __align__(16) float g_h2[(size_t)NN * C2];
__device__ float g_as2[NN];
__device__ float g_ad2[NN];

// ---------------- edge dtype detection ----------------
__global__ void k_detect(const int* __restrict__ e32) {
    if (threadIdx.x == 0) {
        int all_zero = 1;
        #pragma unroll
        for (int i = 0; i < 32; i++)
            if (e32[2 * i + 1] != 0) all_zero = 0;
        g_is64 = all_zero;
    }
}

// ---------------- CSR build ----------------
__global__ void k_zero_deg() {
    int i = blockIdx.x * blockDim.x + threadIdx.x;
    if (i < NN) g_deg[i] = 0;
}

__device__ __forceinline__ int clampN(int v) {
    v = v < 0 ? 0 : v;
    return v >= NN ? NN - 1 : v;
}

__global__ void k_edges(const int* __restrict__ e32) {
    int i = blockIdx.x * blockDim.x + threadIdx.x;
    if (i >= E_TOT) return;
    int s, d;
    if (i < E_RAW) {
        if (g_is64) {
            const int2* e64 = (const int2*)e32;
            s = e64[i].x;
            d = e64[(size_t)E_RAW + i].x;
        } else {
            s = e32[i];
            d = e32[E_RAW + i];
        }
        s = clampN(s);
        d = clampN(d);
    } else {
        s = d = i - E_RAW;
    }
    g_src[i] = s;
    g_dstv[i] = d;
    atomicAdd(&g_deg[d], 1);
}

__global__ void k_scan1() {
    __shared__ int sm[256];
    int tid = threadIdx.x;
    int i = blockIdx.x * 256 + tid;
    int v = (i < NN) ? g_deg[i] : 0;
    sm[tid] = v;
    __syncthreads();
    #pragma unroll
    for (int off = 1; off < 256; off <<= 1) {
        int t = (tid >= off) ? sm[tid - off] : 0;
        __syncthreads();
        sm[tid] += t;
        __syncthreads();
    }
    if (i < NN) g_off[i] = sm[tid] - v;
    if (tid == 255) g_bsum[blockIdx.x] = sm[255];
}

__global__ void k_scan2() {
    __shared__ int sm[NB_SCAN];
    int tid = threadIdx.x;
    int v = (tid < NB_SCAN) ? g_bsum[tid] : 0;
    if (tid < NB_SCAN) sm[tid] = v;
    __syncthreads();
    for (int off = 1; off < NB_SCAN; off <<= 1) {
        int t = (tid >= off && tid < NB_SCAN) ? sm[tid - off] : 0;
        __syncthreads();
        if (tid < NB_SCAN) sm[tid] += t;
        __syncthreads();
    }
    if (tid < NB_SCAN) g_boff[tid] = sm[tid] - v;
    if (tid == 0) g_off[NN] = E_TOT;
}

__global__ void k_scan3() {
    int i = blockIdx.x * 256 + threadIdx.x;
    if (i < NN) {
        int o = g_off[i] + g_boff[blockIdx.x];
        g_off[i] = o;
        g_cur[i] = o;
    }
}

__global__ void k_fill() {
    int i = blockIdx.x * blockDim.x + threadIdx.x;
    if (i >= E_TOT) return;
    int d = g_dstv[i];
    int pos = atomicAdd(&g_cur[d], 1);
    g_csr_src[pos] = g_src[i];
}

// ---------------- tf32 helpers ----------------
__device__ __forceinline__ uint32_t f2tf32(float v) {
    uint32_t r;
    asm("cvt.rna.tf32.f32 %0, %1;" : "=r"(r) : "f"(v));
    return r;
}
__device__ __forceinline__ void mma_tf32(float* c, const uint32_t* a, uint32_t b0, uint32_t b1) {
    asm volatile(
        "mma.sync.aligned.m16n8k8.row.col.f32.tf32.tf32.f32 "
        "{%0,%1,%2,%3}, {%4,%5,%6,%7}, {%8,%9}, {%0,%1,%2,%3};"
        : "+f"(c[0]), "+f"(c[1]), "+f"(c[2]), "+f"(c[3])
        : "r"(a[0]), "r"(a[1]), "r"(a[2]), "r"(a[3]), "r"(b0), "r"(b1));
}

// split W1 into tf32 hi/lo (once)
__global__ void k_prep(const float* __restrict__ W1) {
    int i = blockIdx.x * 256 + threadIdx.x;
    if (i < F_IN * F1) {
        float v = W1[i];
        uint32_t hb = f2tf32(v);
        float h = __uint_as_float(hb);
        g_W1h[i] = h;
        g_W1l[i] = __uint_as_float(f2tf32(v - h));
    }
}

// ===== GEMM1 via mma.sync tf32 3-term split + fused attention coefficients ==
// grid: 391 blocks of 256 thr; tile 128 rows x 64 cols; K=512 in BK=32 chunks.
__global__ void __launch_bounds__(256) k_gemm1_mma(
    const float* __restrict__ x,
    const float* __restrict__ att_s, const float* __restrict__ att_d) {
    __shared__ float As[BM][BK + 1];
    __shared__ float Bh[BK][F1 + 1];
    __shared__ float Bl[BK][F1 + 1];
    __shared__ float Sa[F1], Sd[F1];
    const int tid = threadIdx.x, wid = tid >> 5, lane = tid & 31;
    const int g = lane >> 2, t = lane & 3;
    const int m0 = blockIdx.x * BM;
    if (tid < F1) {
        Sa[tid] = att_s[tid];
        Sd[tid] = att_d[tid];
    }
    float acc[8][4] = {};

    for (int ck = 0; ck < F_IN / BK; ck++) {
        const int k0g = ck * BK;
        __syncthreads();
        // stage A: 128x32 fp32 (4 float4 per thread)
        #pragma unroll
        for (int i = 0; i < 4; i++) {
            int f = tid + i * 256;
            int r = f >> 3, c4 = (f & 7) * 4;
            float4 v = make_float4(0.f, 0.f, 0.f, 0.f);
            if (m0 + r < NN) v = *(const float4*)(x + (size_t)(m0 + r) * F_IN + k0g + c4);
            As[r][c4] = v.x; As[r][c4 + 1] = v.y; As[r][c4 + 2] = v.z; As[r][c4 + 3] = v.w;
        }
        // stage Bh/Bl: 32x64 each (2 float4 per thread per array)
        #pragma unroll
        for (int i = 0; i < 2; i++) {
            int f = tid + i * 256;
            int r = f >> 4, c4 = (f & 15) * 4;
            float4 v = *(const float4*)(g_W1h + (size_t)(k0g + r) * F1 + c4);
            Bh[r][c4] = v.x; Bh[r][c4 + 1] = v.y; Bh[r][c4 + 2] = v.z; Bh[r][c4 + 3] = v.w;
            float4 w = *(const float4*)(g_W1l + (size_t)(k0g + r) * F1 + c4);
            Bl[r][c4] = w.x; Bl[r][c4 + 1] = w.y; Bl[r][c4 + 2] = w.z; Bl[r][c4 + 3] = w.w;
        }
        __syncthreads();
        const int ar = wid * 16;
        #pragma unroll
        for (int ks = 0; ks < BK / 8; ks++) {
            const int k0 = ks * 8;
            float a0 = As[ar + g][k0 + t];
            float a1 = As[ar + g + 8][k0 + t];
            float a2 = As[ar + g][k0 + t + 4];
            float a3 = As[ar + g + 8][k0 + t + 4];
            uint32_t ah[4], al[4];
            ah[0] = f2tf32(a0); al[0] = f2tf32(a0 - __uint_as_float(ah[0]));
            ah[1] = f2tf32(a1); al[1] = f2tf32(a1 - __uint_as_float(ah[1]));
            ah[2] = f2tf32(a2); al[2] = f2tf32(a2 - __uint_as_float(ah[2]));
            ah[3] = f2tf32(a3); al[3] = f2tf32(a3 - __uint_as_float(ah[3]));
            #pragma unroll
            for (int j = 0; j < 8; j++) {
                uint32_t bh0 = __float_as_uint(Bh[k0 + t][j * 8 + g]);
                uint32_t bh1 = __float_as_uint(Bh[k0 + t + 4][j * 8 + g]);
                uint32_t bl0 = __float_as_uint(Bl[k0 + t][j * 8 + g]);
                uint32_t bl1 = __float_as_uint(Bl[k0 + t + 4][j * 8 + g]);
                mma_tf32(acc[j], ah, bh0, bh1);
                mma_tf32(acc[j], ah, bl0, bl1);
                mma_tf32(acc[j], al, bh0, bh1);
            }
        }
    }

    // epilogue: store h1 + fused a_src/a_dst (head j == n-tile j)
    const int r0 = m0 + wid * 16 + g, r1 = r0 + 8;
    #pragma unroll
    for (int j = 0; j < 8; j++) {
        const int cl = j * 8 + 2 * t;
        if (r0 < NN) *(float2*)(g_h1 + (size_t)r0 * F1 + cl) = make_float2(acc[j][0], acc[j][1]);
        if (r1 < NN) *(float2*)(g_h1 + (size_t)r1 * F1 + cl) = make_float2(acc[j][2], acc[j][3]);
        float s0 = acc[j][0] * Sa[cl] + acc[j][1] * Sa[cl + 1];
        float d0 = acc[j][0] * Sd[cl] + acc[j][1] * Sd[cl + 1];
        float s1 = acc[j][2] * Sa[cl] + acc[j][3] * Sa[cl + 1];
        float d1 = acc[j][2] * Sd[cl] + acc[j][3] * Sd[cl + 1];
        #pragma unroll
        for (int o = 1; o <= 2; o <<= 1) {
            s0 += __shfl_xor_sync(0xffffffffu, s0, o);
            d0 += __shfl_xor_sync(0xffffffffu, d0, o);
            s1 += __shfl_xor_sync(0xffffffffu, s1, o);
            d1 += __shfl_xor_sync(0xffffffffu, d1, o);
        }
        if (t == 0) {
            if (r0 < NN) { g_as1[(size_t)r0 * 8 + j] = s0; g_ad1[(size_t)r0 * 8 + j] = d0; }
            if (r1 < NN) { g_as1[(size_t)r1 * 8 + j] = s1; g_ad1[(size_t)r1 * 8 + j] = d1; }
        }
    }
}

// ---------------- GEMM2 (FFMA; small) ----------------
template <int TN, int TK>
__device__ __forceinline__ void gemm_body(const float* __restrict__ A,
                                          const float* __restrict__ B,
                                          float* __restrict__ C, int M) {
    __shared__ float As[16][68];
    __shared__ float Bs[16][64];
    int tid = threadIdx.x;
    int ty = tid >> 4, tx = tid & 15;
    int m0 = blockIdx.x * 64;
    float acc[4][4] = {};
    for (int k0 = 0; k0 < TK; k0 += 16) {
        {
            int r = tid >> 2, c4 = (tid & 3) * 4;
            float4 v = make_float4(0.f, 0.f, 0.f, 0.f);
            int m = m0 + r;
            if (m < M) v = *(const float4*)(A + (size_t)m * TK + k0 + c4);
            As[c4 + 0][r] = v.x;
            As[c4 + 1][r] = v.y;
            As[c4 + 2][r] = v.z;
            As[c4 + 3][r] = v.w;
        }
        {
            int kr = tid >> 4, n4 = (tid & 15) * 4;
            float4 v = make_float4(0.f, 0.f, 0.f, 0.f);
            if (n4 < TN) v = *(const float4*)(B + (size_t)(k0 + kr) * TN + n4);
            Bs[kr][n4 + 0] = v.x;
            Bs[kr][n4 + 1] = v.y;
            Bs[kr][n4 + 2] = v.z;
            Bs[kr][n4 + 3] = v.w;
        }
        __syncthreads();
        #pragma unroll
        for (int kk = 0; kk < 16; kk++) {
            float4 a = *(const float4*)&As[kk][ty * 4];
            float4 b = *(const float4*)&Bs[kk][tx * 4];
            float av[4] = {a.x, a.y, a.z, a.w};
            float bv[4] = {b.x, b.y, b.z, b.w};
            #pragma unroll
            for (int i = 0; i < 4; i++)
                #pragma unroll
                for (int j = 0; j < 4; j++) acc[i][j] += av[i] * bv[j];
        }
        __syncthreads();
    }
    #pragma unroll
    for (int i = 0; i < 4; i++) {
        int m = m0 + ty * 4 + i;
        if (m < M && tx * 4 < TN) {
            float4 v = make_float4(acc[i][0], acc[i][1], acc[i][2], acc[i][3]);
            *(float4*)(C + (size_t)m * TN + tx * 4) = v;
        }
    }
}

__global__ void k_gemm2(const float* __restrict__ B) {
    gemm_body<C2, F1>(g_x1, B, g_h2, NN);
}

__global__ void k_a2(const float* __restrict__ att_s, const float* __restrict__ att_d) {
    int n = blockIdx.x * blockDim.x + threadIdx.x;
    if (n >= NN) return;
    const float* hp = g_h2 + (size_t)n * C2;
    float s = 0.f, d = 0.f;
    #pragma unroll
    for (int c = 0; c < C2; c++) {
        float v = hp[c];
        s += v * att_s[c];
        d += v * att_d[c];
    }
    g_as2[n] = s;
    g_ad2[n] = d;
}

__device__ __forceinline__ float lrelu(float e) { return e > 0.f ? e : 0.2f * e; }

// -------- layer 1 attention: warp/node, single edge pass, deferred norm ------
__global__ void k_attn1(const float* __restrict__ b1) {
    int warp = threadIdx.x >> 5, lane = threadIdx.x & 31;
    int n = blockIdx.x * 8 + warp;
    if (n >= NN) return;
    int beg = g_off[n], end = g_off[n + 1];

    int c0 = lane, c1 = lane + 32;
    int ha = lane >> 3, hb = ha + 4;
    float ada = g_ad1[(size_t)n * 8 + ha];
    float adb = g_ad1[(size_t)n * 8 + hb];
    float acc0 = 0.f, acc1 = 0.f, dna = 0.f, dnb = 0.f;
    for (int i = beg; i < end; i++) {
        int s = g_csr_src[i];
        float wa = __expf(lrelu(g_as1[(size_t)s * 8 + ha] + ada));
        float wb = __expf(lrelu(g_as1[(size_t)s * 8 + hb] + adb));
        acc0 += wa * g_h1[(size_t)s * F1 + c0];
        acc1 += wb * g_h1[(size_t)s * F1 + c1];
        dna += wa;
        dnb += wb;
    }
    g_x1[(size_t)n * F1 + c0] = fmaxf(acc0 / dna + b1[c0], 0.f);
    g_x1[(size_t)n * F1 + c1] = fmaxf(acc1 / dnb + b1[c1], 0.f);
}

// -------- layer 2 attention + log_softmax: warp/node, single edge pass ------
__global__ void k_attn2(const float* __restrict__ b2, float* __restrict__ out) {
    int warp = threadIdx.x >> 5, lane = threadIdx.x & 31;
    int n = blockIdx.x * 8 + warp;
    if (n >= NN) return;
    int beg = g_off[n], end = g_off[n + 1];
    float ad = g_ad2[n];

    float acc0 = 0.f, acc1 = 0.f, dn = 0.f;
    for (int i = beg; i < end; i++) {
        int s = g_csr_src[i];
        float w = __expf(lrelu(g_as2[s] + ad));
        acc0 += w * g_h2[(size_t)s * C2 + lane];
        if (lane < 8) acc1 += w * g_h2[(size_t)s * C2 + 32 + lane];
        dn += w;
    }
    float inv = 1.f / dn;

    float v0 = acc0 * inv + b2[lane];
    float v1r = (lane < 8) ? (acc1 * inv + b2[32 + lane]) : -1e30f;
    float m = fmaxf(v0, v1r);
    #pragma unroll
    for (int o = 16; o > 0; o >>= 1) m = fmaxf(m, __shfl_xor_sync(0xffffffffu, m, o));
    float se = __expf(v0 - m) + ((lane < 8) ? __expf(v1r - m) : 0.f);
    #pragma unroll
    for (int o = 16; o > 0; o >>= 1) se += __shfl_xor_sync(0xffffffffu, se, o);
    float ls = m + logf(se);

    out[(size_t)n * C2 + lane] = v0 - ls;
    if (lane < 8) out[(size_t)n * C2 + 32 + lane] = v1r - ls;
}

// ---------------- launch ----------------
extern "C" void kernel_launch(void* const* d_in, const int* in_sizes, int n_in,
                              void* d_out, int out_size) {
    const float* x   = (const float*)d_in[0];
    const int*   ei  = (const int*)d_in[1];
    const float* W1  = (const float*)d_in[2];
    const float* as1 = (const float*)d_in[3];
    const float* ad1 = (const float*)d_in[4];
    const float* b1  = (const float*)d_in[5];
    const float* W2  = (const float*)d_in[6];
    const float* as2 = (const float*)d_in[7];
    const float* ad2 = (const float*)d_in[8];
    const float* b2  = (const float*)d_in[9];
    float*       out = (float*)d_out;

    k_detect<<<1, 32>>>(ei);
    k_zero_deg<<<(NN + 255) / 256, 256>>>();
    k_edges<<<(E_TOT + 255) / 256, 256>>>(ei);
    k_scan1<<<NB_SCAN, 256>>>();
    k_scan2<<<1, 256>>>();
    k_scan3<<<NB_SCAN, 256>>>();
    k_fill<<<(E_TOT + 255) / 256, 256>>>();

    k_prep<<<(F_IN * F1 + 255) / 256, 256>>>(W1);
    k_gemm1_mma<<<(NN + BM - 1) / BM, 256>>>(x, as1, ad1);
    k_attn1<<<(NN + 7) / 8, 256>>>(b1);

    k_gemm2<<<(NN + 63) / 64, 256>>>(W2);
    k_a2<<<(NN + 255) / 256, 256>>>(as2, ad2);
    k_attn2<<<(NN + 7) / 8, 256>>>(b2, out);
}

// round 15
// speedup vs baseline: 1.3575x; 1.3575x over previous
#include <cuda_runtime.h>
#include <cuda_bf16.h>
#include <cstdint>

#define NN 50000
#define E_RAW 1600000
#define E_TOT (E_RAW + NN)
#define F_IN 512
#define H1N 8
#define C1N 8
#define F1 64
#define C2 40
#define NB_SCAN ((NN + 255) / 256)
#define BM 128
#define BK 32
#define KP2 (F_IN / 2)   // 256 u32 per n-row in packed W1

// ---------------- scratch (static __device__ — no allocation) ----------------
__device__ int   g_src[E_TOT];
__device__ int   g_dstv[E_TOT];
__device__ int   g_csr_src[E_TOT];
__device__ int   g_deg[NN];
__device__ int   g_off[NN + 1];
__device__ int   g_cur[NN];
__device__ int   g_bsum[NB_SCAN];
__device__ int   g_boff[NB_SCAN];
__device__ int   g_is64;
__device__ __align__(16) uint32_t g_Bh[F1 * KP2];  // W1 hi, [n][k/2] bf16x2
__device__ __align__(16) uint32_t g_Bl[F1 * KP2];  // W1 lo
__device__ __align__(16) float g_h1[(size_t)NN * F1];
__device__ __align__(16) float g_x1[(size_t)NN * F1];
__device__ __align__(16) float g_as1[(size_t)NN * H1N];
__device__ __align__(16) float g_ad1[(size_t)NN * H1N];
__device__ __align__(16) float g_h2[(size_t)NN * C2];
__device__ float g_as2[NN];
__device__ float g_ad2[NN];

// ---------------- edge dtype detection ----------------
__global__ void k_detect(const int* __restrict__ e32) {
    if (threadIdx.x == 0) {
        int all_zero = 1;
        #pragma unroll
        for (int i = 0; i < 32; i++)
            if (e32[2 * i + 1] != 0) all_zero = 0;
        g_is64 = all_zero;
    }
}

// ---------------- CSR build ----------------
__global__ void k_zero_deg() {
    int i = blockIdx.x * blockDim.x + threadIdx.x;
    if (i < NN) g_deg[i] = 0;
}

__device__ __forceinline__ int clampN(int v) {
    v = v < 0 ? 0 : v;
    return v >= NN ? NN - 1 : v;
}

__global__ void k_edges(const int* __restrict__ e32) {
    int i = blockIdx.x * blockDim.x + threadIdx.x;
    if (i >= E_TOT) return;
    int s, d;
    if (i < E_RAW) {
        if (g_is64) {
            const int2* e64 = (const int2*)e32;
            s = e64[i].x;
            d = e64[(size_t)E_RAW + i].x;
        } else {
            s = e32[i];
            d = e32[E_RAW + i];
        }
        s = clampN(s);
        d = clampN(d);
    } else {
        s = d = i - E_RAW;
    }
    g_src[i] = s;
    g_dstv[i] = d;
    atomicAdd(&g_deg[d], 1);
}

__global__ void k_scan1() {
    __shared__ int sm[256];
    int tid = threadIdx.x;
    int i = blockIdx.x * 256 + tid;
    int v = (i < NN) ? g_deg[i] : 0;
    sm[tid] = v;
    __syncthreads();
    #pragma unroll
    for (int off = 1; off < 256; off <<= 1) {
        int t = (tid >= off) ? sm[tid - off] : 0;
        __syncthreads();
        sm[tid] += t;
        __syncthreads();
    }
    if (i < NN) g_off[i] = sm[tid] - v;
    if (tid == 255) g_bsum[blockIdx.x] = sm[255];
}

__global__ void k_scan2() {
    __shared__ int sm[NB_SCAN];
    int tid = threadIdx.x;
    int v = (tid < NB_SCAN) ? g_bsum[tid] : 0;
    if (tid < NB_SCAN) sm[tid] = v;
    __syncthreads();
    for (int off = 1; off < NB_SCAN; off <<= 1) {
        int t = (tid >= off && tid < NB_SCAN) ? sm[tid - off] : 0;
        __syncthreads();
        if (tid < NB_SCAN) sm[tid] += t;
        __syncthreads();
    }
    if (tid < NB_SCAN) g_boff[tid] = sm[tid] - v;
    if (tid == 0) g_off[NN] = E_TOT;
}

__global__ void k_scan3() {
    int i = blockIdx.x * 256 + threadIdx.x;
    if (i < NN) {
        int o = g_off[i] + g_boff[blockIdx.x];
        g_off[i] = o;
        g_cur[i] = o;
    }
}

__global__ void k_fill() {
    int i = blockIdx.x * blockDim.x + threadIdx.x;
    if (i >= E_TOT) return;
    int d = g_dstv[i];
    int pos = atomicAdd(&g_cur[d], 1);
    g_csr_src[pos] = g_src[i];
}

// ---------------- bf16 split helpers ----------------
__device__ __forceinline__ void split2(float v0, float v1, uint32_t& hi, uint32_t& lo) {
    __nv_bfloat162 h = __floats2bfloat162_rn(v0, v1);
    float h0 = __bfloat162float(__low2bfloat16(h));
    float h1 = __bfloat162float(__high2bfloat16(h));
    __nv_bfloat162 l = __floats2bfloat162_rn(v0 - h0, v1 - h1);
    hi = *(uint32_t*)&h;
    lo = *(uint32_t*)&l;
}
__device__ __forceinline__ void mma_bf16(float* c, const uint32_t* a, uint32_t b0, uint32_t b1) {
    asm volatile(
        "mma.sync.aligned.m16n8k16.row.col.f32.bf16.bf16.f32 "
        "{%0,%1,%2,%3}, {%4,%5,%6,%7}, {%8,%9}, {%0,%1,%2,%3};"
        : "+f"(c[0]), "+f"(c[1]), "+f"(c[2]), "+f"(c[3])
        : "r"(a[0]), "r"(a[1]), "r"(a[2]), "r"(a[3]), "r"(b0), "r"(b1));
}

// pack W1 [k][n] fp32 -> [n][k/2] bf16x2 hi/lo (once, tiny)
__global__ void k_prep(const float* __restrict__ W1) {
    int i = blockIdx.x * 256 + threadIdx.x;
    if (i >= F1 * KP2) return;
    int n = i / KP2, kp = i % KP2;
    float v0 = W1[(size_t)(2 * kp) * F1 + n];
    float v1 = W1[(size_t)(2 * kp + 1) * F1 + n];
    uint32_t hi, lo;
    split2(v0, v1, hi, lo);
    g_Bh[i] = hi;
    g_Bl[i] = lo;
}

// ===== GEMM1: mma.sync bf16 3-term split, conflict-free SMEM, fused a1 ======
// tile 128x64, K=512 in BK=32 chunks; 256 thr (8 warps of 16x64 each... 8 warps x 16 rows)
__global__ void __launch_bounds__(256) k_gemm1_mma(
    const float* __restrict__ x,
    const float* __restrict__ att_s, const float* __restrict__ att_d) {
    __shared__ uint32_t Ah[BM][20], Al[BM][20];   // bf16x2, stride 20 => conflict-free
    __shared__ uint32_t Bh[F1][20], Bl[F1][20];
    __shared__ float Sa[F1], Sd[F1];
    const int tid = threadIdx.x, wid = tid >> 5, lane = tid & 31;
    const int g = lane >> 2, t = lane & 3;
    const int m0 = blockIdx.x * BM;
    if (tid < F1) {
        Sa[tid] = att_s[tid];
        Sd[tid] = att_d[tid];
    }
    float acc[8][4] = {};

    for (int ck = 0; ck < F_IN / BK; ck++) {
        __syncthreads();
        // stage A: 128 rows x 32 k (fp32 -> hi/lo bf16x2). 1024 float4s / 256 thr.
        #pragma unroll
        for (int i = 0; i < 4; i++) {
            int f = tid + i * 256;
            int r = f >> 3, q = f & 7;           // q: which float4 in the 32-k row
            float4 v = make_float4(0.f, 0.f, 0.f, 0.f);
            if (m0 + r < NN)
                v = *(const float4*)(x + (size_t)(m0 + r) * F_IN + ck * BK + q * 4);
            uint32_t h0, l0, h1, l1;
            split2(v.x, v.y, h0, l0);
            split2(v.z, v.w, h1, l1);
            Ah[r][q * 2] = h0; Ah[r][q * 2 + 1] = h1;
            Al[r][q * 2] = l0; Al[r][q * 2 + 1] = l1;
        }
        // stage B: 64 n-rows x 16 u32 each, uint4 loads (prepacked bf16x2)
        {
            int n = tid >> 2, i4 = (tid & 3) * 4;
            uint4 vh = *(const uint4*)(g_Bh + (size_t)n * KP2 + ck * 16 + i4);
            Bh[n][i4] = vh.x; Bh[n][i4 + 1] = vh.y; Bh[n][i4 + 2] = vh.z; Bh[n][i4 + 3] = vh.w;
            uint4 vl = *(const uint4*)(g_Bl + (size_t)n * KP2 + ck * 16 + i4);
            Bl[n][i4] = vl.x; Bl[n][i4 + 1] = vl.y; Bl[n][i4 + 2] = vl.z; Bl[n][i4 + 3] = vl.w;
        }
        __syncthreads();
        const int ar = wid * 16;
        #pragma unroll
        for (int ks = 0; ks < 2; ks++) {
            const int ko = ks * 8;
            uint32_t ah[4], al[4];
            ah[0] = Ah[ar + g][ko + t];     al[0] = Al[ar + g][ko + t];
            ah[1] = Ah[ar + g + 8][ko + t]; al[1] = Al[ar + g + 8][ko + t];
            ah[2] = Ah[ar + g][ko + t + 4]; al[2] = Al[ar + g][ko + t + 4];
            ah[3] = Ah[ar + g + 8][ko + t + 4]; al[3] = Al[ar + g + 8][ko + t + 4];
            #pragma unroll
            for (int j = 0; j < 8; j++) {
                const int n = j * 8 + g;
                uint32_t bh0 = Bh[n][ko + t], bh1 = Bh[n][ko + t + 4];
                uint32_t bl0 = Bl[n][ko + t], bl1 = Bl[n][ko + t + 4];
                mma_bf16(acc[j], ah, bh0, bh1);
                mma_bf16(acc[j], ah, bl0, bl1);
                mma_bf16(acc[j], al, bh0, bh1);
            }
        }
    }

    // epilogue: store h1 + fused a_src/a_dst (n-tile j == head j)
    const int r0 = m0 + wid * 16 + g, r1 = r0 + 8;
    #pragma unroll
    for (int j = 0; j < 8; j++) {
        const int cl = j * 8 + 2 * t;
        if (r0 < NN) *(float2*)(g_h1 + (size_t)r0 * F1 + cl) = make_float2(acc[j][0], acc[j][1]);
        if (r1 < NN) *(float2*)(g_h1 + (size_t)r1 * F1 + cl) = make_float2(acc[j][2], acc[j][3]);
        float s0 = acc[j][0] * Sa[cl] + acc[j][1] * Sa[cl + 1];
        float d0 = acc[j][0] * Sd[cl] + acc[j][1] * Sd[cl + 1];
        float s1 = acc[j][2] * Sa[cl] + acc[j][3] * Sa[cl + 1];
        float d1 = acc[j][2] * Sd[cl] + acc[j][3] * Sd[cl + 1];
        #pragma unroll
        for (int o = 1; o <= 2; o <<= 1) {
            s0 += __shfl_xor_sync(0xffffffffu, s0, o);
            d0 += __shfl_xor_sync(0xffffffffu, d0, o);
            s1 += __shfl_xor_sync(0xffffffffu, s1, o);
            d1 += __shfl_xor_sync(0xffffffffu, d1, o);
        }
        if (t == 0) {
            if (r0 < NN) { g_as1[(size_t)r0 * 8 + j] = s0; g_ad1[(size_t)r0 * 8 + j] = d0; }
            if (r1 < NN) { g_as1[(size_t)r1 * 8 + j] = s1; g_ad1[(size_t)r1 * 8 + j] = d1; }
        }
    }
}

// ---------------- GEMM2 (FFMA; small) ----------------
template <int TN, int TK>
__device__ __forceinline__ void gemm_body(const float* __restrict__ A,
                                          const float* __restrict__ B,
                                          float* __restrict__ C, int M) {
    __shared__ float As[16][68];
    __shared__ float Bs[16][64];
    int tid = threadIdx.x;
    int ty = tid >> 4, tx = tid & 15;
    int m0 = blockIdx.x * 64;
    float acc[4][4] = {};
    for (int k0 = 0; k0 < TK; k0 += 16) {
        {
            int r = tid >> 2, c4 = (tid & 3) * 4;
            float4 v = make_float4(0.f, 0.f, 0.f, 0.f);
            int m = m0 + r;
            if (m < M) v = *(const float4*)(A + (size_t)m * TK + k0 + c4);
            As[c4 + 0][r] = v.x;
            As[c4 + 1][r] = v.y;
            As[c4 + 2][r] = v.z;
            As[c4 + 3][r] = v.w;
        }
        {
            int kr = tid >> 4, n4 = (tid & 15) * 4;
            float4 v = make_float4(0.f, 0.f, 0.f, 0.f);
            if (n4 < TN) v = *(const float4*)(B + (size_t)(k0 + kr) * TN + n4);
            Bs[kr][n4 + 0] = v.x;
            Bs[kr][n4 + 1] = v.y;
            Bs[kr][n4 + 2] = v.z;
            Bs[kr][n4 + 3] = v.w;
        }
        __syncthreads();
        #pragma unroll
        for (int kk = 0; kk < 16; kk++) {
            float4 a = *(const float4*)&As[kk][ty * 4];
            float4 b = *(const float4*)&Bs[kk][tx * 4];
            float av[4] = {a.x, a.y, a.z, a.w};
            float bv[4] = {b.x, b.y, b.z, b.w};
            #pragma unroll
            for (int i = 0; i < 4; i++)
                #pragma unroll
                for (int j = 0; j < 4; j++) acc[i][j] += av[i] * bv[j];
        }
        __syncthreads();
    }
    #pragma unroll
    for (int i = 0; i < 4; i++) {
        int m = m0 + ty * 4 + i;
        if (m < M && tx * 4 < TN) {
            float4 v = make_float4(acc[i][0], acc[i][1], acc[i][2], acc[i][3]);
            *(float4*)(C + (size_t)m * TN + tx * 4) = v;
        }
    }
}

__global__ void k_gemm2(const float* __restrict__ B) {
    gemm_body<C2, F1>(g_x1, B, g_h2, NN);
}

__global__ void k_a2(const float* __restrict__ att_s, const float* __restrict__ att_d) {
    int n = blockIdx.x * blockDim.x + threadIdx.x;
    if (n >= NN) return;
    const float* hp = g_h2 + (size_t)n * C2;
    float s = 0.f, d = 0.f;
    #pragma unroll
    for (int c = 0; c < C2; c++) {
        float v = hp[c];
        s += v * att_s[c];
        d += v * att_d[c];
    }
    g_as2[n] = s;
    g_ad2[n] = d;
}

__device__ __forceinline__ float lrelu(float e) { return e > 0.f ? e : 0.2f * e; }

// -------- layer 1 attention: warp/node, single edge pass, deferred norm ------
__global__ void k_attn1(const float* __restrict__ b1) {
    int warp = threadIdx.x >> 5, lane = threadIdx.x & 31;
    int n = blockIdx.x * 8 + warp;
    if (n >= NN) return;
    int beg = g_off[n], end = g_off[n + 1];

    int c0 = lane, c1 = lane + 32;
    int ha = lane >> 3, hb = ha + 4;
    float ada = g_ad1[(size_t)n * 8 + ha];
    float adb = g_ad1[(size_t)n * 8 + hb];
    float acc0 = 0.f, acc1 = 0.f, dna = 0.f, dnb = 0.f;
    for (int i = beg; i < end; i++) {
        int s = g_csr_src[i];
        float wa = __expf(lrelu(g_as1[(size_t)s * 8 + ha] + ada));
        float wb = __expf(lrelu(g_as1[(size_t)s * 8 + hb] + adb));
        acc0 += wa * g_h1[(size_t)s * F1 + c0];
        acc1 += wb * g_h1[(size_t)s * F1 + c1];
        dna += wa;
        dnb += wb;
    }
    g_x1[(size_t)n * F1 + c0] = fmaxf(acc0 / dna + b1[c0], 0.f);
    g_x1[(size_t)n * F1 + c1] = fmaxf(acc1 / dnb + b1[c1], 0.f);
}

// -------- layer 2 attention + log_softmax: warp/node, single edge pass ------
__global__ void k_attn2(const float* __restrict__ b2, float* __restrict__ out) {
    int warp = threadIdx.x >> 5, lane = threadIdx.x & 31;
    int n = blockIdx.x * 8 + warp;
    if (n >= NN) return;
    int beg = g_off[n], end = g_off[n + 1];
    float ad = g_ad2[n];

    float acc0 = 0.f, acc1 = 0.f, dn = 0.f;
    for (int i = beg; i < end; i++) {
        int s = g_csr_src[i];
        float w = __expf(lrelu(g_as2[s] + ad));
        acc0 += w * g_h2[(size_t)s * C2 + lane];
        if (lane < 8) acc1 += w * g_h2[(size_t)s * C2 + 32 + lane];
        dn += w;
    }
    float inv = 1.f / dn;

    float v0 = acc0 * inv + b2[lane];
    float v1r = (lane < 8) ? (acc1 * inv + b2[32 + lane]) : -1e30f;
    float m = fmaxf(v0, v1r);
    #pragma unroll
    for (int o = 16; o > 0; o >>= 1) m = fmaxf(m, __shfl_xor_sync(0xffffffffu, m, o));
    float se = __expf(v0 - m) + ((lane < 8) ? __expf(v1r - m) : 0.f);
    #pragma unroll
    for (int o = 16; o > 0; o >>= 1) se += __shfl_xor_sync(0xffffffffu, se, o);
    float ls = m + logf(se);

    out[(size_t)n * C2 + lane] = v0 - ls;
    if (lane < 8) out[(size_t)n * C2 + 32 + lane] = v1r - ls;
}

// ---------------- launch ----------------
extern "C" void kernel_launch(void* const* d_in, const int* in_sizes, int n_in,
                              void* d_out, int out_size) {
    const float* x   = (const float*)d_in[0];
    const int*   ei  = (const int*)d_in[1];
    const float* W1  = (const float*)d_in[2];
    const float* as1 = (const float*)d_in[3];
    const float* ad1 = (const float*)d_in[4];
    const float* b1  = (const float*)d_in[5];
    const float* W2  = (const float*)d_in[6];
    const float* as2 = (const float*)d_in[7];
    const float* ad2 = (const float*)d_in[8];
    const float* b2  = (const float*)d_in[9];
    float*       out = (float*)d_out;

    k_detect<<<1, 32>>>(ei);
    k_zero_deg<<<(NN + 255) / 256, 256>>>();
    k_edges<<<(E_TOT + 255) / 256, 256>>>(ei);
    k_scan1<<<NB_SCAN, 256>>>();
    k_scan2<<<1, 256>>>();
    k_scan3<<<NB_SCAN, 256>>>();
    k_fill<<<(E_TOT + 255) / 256, 256>>>();

    k_prep<<<(F1 * KP2 + 255) / 256, 256>>>(W1);
    k_gemm1_mma<<<(NN + BM - 1) / BM, 256>>>(x, as1, ad1);
    k_attn1<<<(NN + 7) / 8, 256>>>(b1);

    k_gemm2<<<(NN + 63) / 64, 256>>>(W2);
    k_a2<<<(NN + 255) / 256, 256>>>(as2, ad2);
    k_attn2<<<(NN + 7) / 8, 256>>>(b2, out);
}

// round 16
// speedup vs baseline: 1.7240x; 1.2700x over previous
#include <cuda_runtime.h>
#include <cuda_bf16.h>
#include <cstdint>

#define NN 50000
#define E_RAW 1600000
#define E_TOT (E_RAW + NN)
#define F_IN 512
#define H1N 8
#define C1N 8
#define F1 64
#define C2 40
#define NB_SCAN ((NN + 255) / 256)
#define BM 128
#define BK 32
#define KP2 (F_IN / 2)

// ---------------- scratch (static __device__ — no allocation) ----------------
__device__ int   g_src[E_TOT];
__device__ int   g_dstv[E_TOT];
__device__ int   g_csr_src[E_TOT];
__device__ int   g_deg[NN];
__device__ int   g_off[NN + 1];
__device__ int   g_cur[NN];
__device__ int   g_bsum[NB_SCAN];
__device__ int   g_boff[NB_SCAN];
__device__ int   g_is64;
__device__ __align__(16) uint32_t g_Bh[F1 * KP2];
__device__ __align__(16) uint32_t g_Bl[F1 * KP2];
__device__ __align__(16) float g_h1[(size_t)NN * F1];
__device__ __align__(16) float g_x1[(size_t)NN * F1];
__device__ __align__(16) float g_as1[(size_t)NN * H1N];
__device__ __align__(16) float g_ad1[(size_t)NN * H1N];
__device__ __align__(16) float g_h2[(size_t)NN * C2];
__device__ float g_as2[NN];
__device__ float g_ad2[NN];

// ---------------- init: zero degrees + edge dtype detection ----------------
__global__ void k_init(const int* __restrict__ e32) {
    int i = blockIdx.x * 256 + threadIdx.x;
    if (i < NN) g_deg[i] = 0;
    if (blockIdx.x == 0 && threadIdx.x == 0) {
        int all_zero = 1;
        #pragma unroll
        for (int q = 0; q < 32; q++)
            if (e32[2 * q + 1] != 0) all_zero = 0;
        g_is64 = all_zero;
    }
}

__device__ __forceinline__ int clampN(int v) {
    v = v < 0 ? 0 : v;
    return v >= NN ? NN - 1 : v;
}

__global__ void k_edges(const int* __restrict__ e32) {
    int i = blockIdx.x * blockDim.x + threadIdx.x;
    if (i >= E_TOT) return;
    int s, d;
    if (i < E_RAW) {
        if (g_is64) {
            const int2* e64 = (const int2*)e32;
            s = e64[i].x;
            d = e64[(size_t)E_RAW + i].x;
        } else {
            s = e32[i];
            d = e32[E_RAW + i];
        }
        s = clampN(s);
        d = clampN(d);
    } else {
        s = d = i - E_RAW;
    }
    g_src[i] = s;
    g_dstv[i] = d;
    atomicAdd(&g_deg[d], 1);
}

__global__ void k_scan1() {
    __shared__ int sm[256];
    int tid = threadIdx.x;
    int i = blockIdx.x * 256 + tid;
    int v = (i < NN) ? g_deg[i] : 0;
    sm[tid] = v;
    __syncthreads();
    #pragma unroll
    for (int off = 1; off < 256; off <<= 1) {
        int t = (tid >= off) ? sm[tid - off] : 0;
        __syncthreads();
        sm[tid] += t;
        __syncthreads();
    }
    if (i < NN) g_off[i] = sm[tid] - v;
    if (tid == 255) g_bsum[blockIdx.x] = sm[255];
}

__global__ void k_scan2() {
    __shared__ int sm[NB_SCAN];
    int tid = threadIdx.x;
    int v = (tid < NB_SCAN) ? g_bsum[tid] : 0;
    if (tid < NB_SCAN) sm[tid] = v;
    __syncthreads();
    for (int off = 1; off < NB_SCAN; off <<= 1) {
        int t = (tid >= off && tid < NB_SCAN) ? sm[tid - off] : 0;
        __syncthreads();
        if (tid < NB_SCAN) sm[tid] += t;
        __syncthreads();
    }
    if (tid < NB_SCAN) g_boff[tid] = sm[tid] - v;
    if (tid == 0) g_off[NN] = E_TOT;
}

__global__ void k_scan3() {
    int i = blockIdx.x * 256 + threadIdx.x;
    if (i < NN) {
        int o = g_off[i] + g_boff[blockIdx.x];
        g_off[i] = o;
        g_cur[i] = o;
    }
}

__global__ void k_fill() {
    int i = blockIdx.x * blockDim.x + threadIdx.x;
    if (i >= E_TOT) return;
    int d = g_dstv[i];
    int pos = atomicAdd(&g_cur[d], 1);
    g_csr_src[pos] = g_src[i];
}

// ---------------- bf16 split helpers ----------------
__device__ __forceinline__ void split2(float v0, float v1, uint32_t& hi, uint32_t& lo) {
    __nv_bfloat162 h = __floats2bfloat162_rn(v0, v1);
    float h0 = __bfloat162float(__low2bfloat16(h));
    float h1 = __bfloat162float(__high2bfloat16(h));
    __nv_bfloat162 l = __floats2bfloat162_rn(v0 - h0, v1 - h1);
    hi = *(uint32_t*)&h;
    lo = *(uint32_t*)&l;
}
__device__ __forceinline__ void mma_bf16(float* c, const uint32_t* a, uint32_t b0, uint32_t b1) {
    asm volatile(
        "mma.sync.aligned.m16n8k16.row.col.f32.bf16.bf16.f32 "
        "{%0,%1,%2,%3}, {%4,%5,%6,%7}, {%8,%9}, {%0,%1,%2,%3};"
        : "+f"(c[0]), "+f"(c[1]), "+f"(c[2]), "+f"(c[3])
        : "r"(a[0]), "r"(a[1]), "r"(a[2]), "r"(a[3]), "r"(b0), "r"(b1));
}

__global__ void k_prep(const float* __restrict__ W1) {
    int i = blockIdx.x * 256 + threadIdx.x;
    if (i >= F1 * KP2) return;
    int n = i / KP2, kp = i % KP2;
    float v0 = W1[(size_t)(2 * kp) * F1 + n];
    float v1 = W1[(size_t)(2 * kp + 1) * F1 + n];
    uint32_t hi, lo;
    split2(v0, v1, hi, lo);
    g_Bh[i] = hi;
    g_Bl[i] = lo;
}

// ===== GEMM1: mma.sync bf16 3-term split, conflict-free SMEM, fused a1 ======
__global__ void __launch_bounds__(256) k_gemm1_mma(
    const float* __restrict__ x,
    const float* __restrict__ att_s, const float* __restrict__ att_d) {
    __shared__ uint32_t Ah[BM][20], Al[BM][20];
    __shared__ uint32_t Bh[F1][20], Bl[F1][20];
    __shared__ float Sa[F1], Sd[F1];
    const int tid = threadIdx.x, wid = tid >> 5, lane = tid & 31;
    const int g = lane >> 2, t = lane & 3;
    const int m0 = blockIdx.x * BM;
    if (tid < F1) {
        Sa[tid] = att_s[tid];
        Sd[tid] = att_d[tid];
    }
    float acc[8][4] = {};

    for (int ck = 0; ck < F_IN / BK; ck++) {
        __syncthreads();
        #pragma unroll
        for (int i = 0; i < 4; i++) {
            int f = tid + i * 256;
            int r = f >> 3, q = f & 7;
            float4 v = make_float4(0.f, 0.f, 0.f, 0.f);
            if (m0 + r < NN)
                v = *(const float4*)(x + (size_t)(m0 + r) * F_IN + ck * BK + q * 4);
            uint32_t h0, l0, h1, l1;
            split2(v.x, v.y, h0, l0);
            split2(v.z, v.w, h1, l1);
            Ah[r][q * 2] = h0; Ah[r][q * 2 + 1] = h1;
            Al[r][q * 2] = l0; Al[r][q * 2 + 1] = l1;
        }
        {
            int n = tid >> 2, i4 = (tid & 3) * 4;
            uint4 vh = *(const uint4*)(g_Bh + (size_t)n * KP2 + ck * 16 + i4);
            Bh[n][i4] = vh.x; Bh[n][i4 + 1] = vh.y; Bh[n][i4 + 2] = vh.z; Bh[n][i4 + 3] = vh.w;
            uint4 vl = *(const uint4*)(g_Bl + (size_t)n * KP2 + ck * 16 + i4);
            Bl[n][i4] = vl.x; Bl[n][i4 + 1] = vl.y; Bl[n][i4 + 2] = vl.z; Bl[n][i4 + 3] = vl.w;
        }
        __syncthreads();
        const int ar = wid * 16;
        #pragma unroll
        for (int ks = 0; ks < 2; ks++) {
            const int ko = ks * 8;
            uint32_t ah[4], al[4];
            ah[0] = Ah[ar + g][ko + t];     al[0] = Al[ar + g][ko + t];
            ah[1] = Ah[ar + g + 8][ko + t]; al[1] = Al[ar + g + 8][ko + t];
            ah[2] = Ah[ar + g][ko + t + 4]; al[2] = Al[ar + g][ko + t + 4];
            ah[3] = Ah[ar + g + 8][ko + t + 4]; al[3] = Al[ar + g + 8][ko + t + 4];
            #pragma unroll
            for (int j = 0; j < 8; j++) {
                const int n = j * 8 + g;
                uint32_t bh0 = Bh[n][ko + t], bh1 = Bh[n][ko + t + 4];
                uint32_t bl0 = Bl[n][ko + t], bl1 = Bl[n][ko + t + 4];
                mma_bf16(acc[j], ah, bh0, bh1);
                mma_bf16(acc[j], ah, bl0, bl1);
                mma_bf16(acc[j], al, bh0, bh1);
            }
        }
    }

    const int r0 = m0 + wid * 16 + g, r1 = r0 + 8;
    #pragma unroll
    for (int j = 0; j < 8; j++) {
        const int cl = j * 8 + 2 * t;
        if (r0 < NN) *(float2*)(g_h1 + (size_t)r0 * F1 + cl) = make_float2(acc[j][0], acc[j][1]);
        if (r1 < NN) *(float2*)(g_h1 + (size_t)r1 * F1 + cl) = make_float2(acc[j][2], acc[j][3]);
        float s0 = acc[j][0] * Sa[cl] + acc[j][1] * Sa[cl + 1];
        float d0 = acc[j][0] * Sd[cl] + acc[j][1] * Sd[cl + 1];
        float s1 = acc[j][2] * Sa[cl] + acc[j][3] * Sa[cl + 1];
        float d1 = acc[j][2] * Sd[cl] + acc[j][3] * Sd[cl + 1];
        #pragma unroll
        for (int o = 1; o <= 2; o <<= 1) {
            s0 += __shfl_xor_sync(0xffffffffu, s0, o);
            d0 += __shfl_xor_sync(0xffffffffu, d0, o);
            s1 += __shfl_xor_sync(0xffffffffu, s1, o);
            d1 += __shfl_xor_sync(0xffffffffu, d1, o);
        }
        if (t == 0) {
            if (r0 < NN) { g_as1[(size_t)r0 * 8 + j] = s0; g_ad1[(size_t)r0 * 8 + j] = d0; }
            if (r1 < NN) { g_as1[(size_t)r1 * 8 + j] = s1; g_ad1[(size_t)r1 * 8 + j] = d1; }
        }
    }
}

// ---------------- GEMM2 with fused a2 epilogue ----------------
__global__ void k_gemm2(const float* __restrict__ B,
                        const float* __restrict__ att_s, const float* __restrict__ att_d) {
    __shared__ float As[16][68];
    __shared__ float Bs[16][64];
    __shared__ float Cs[64][41];
    int tid = threadIdx.x;
    int ty = tid >> 4, tx = tid & 15;
    int m0 = blockIdx.x * 64;
    float acc[4][4] = {};
    for (int k0 = 0; k0 < F1; k0 += 16) {
        {
            int r = tid >> 2, c4 = (tid & 3) * 4;
            float4 v = make_float4(0.f, 0.f, 0.f, 0.f);
            int m = m0 + r;
            if (m < NN) v = *(const float4*)(g_x1 + (size_t)m * F1 + k0 + c4);
            As[c4 + 0][r] = v.x;
            As[c4 + 1][r] = v.y;
            As[c4 + 2][r] = v.z;
            As[c4 + 3][r] = v.w;
        }
        {
            int kr = tid >> 4, n4 = (tid & 15) * 4;
            float4 v = make_float4(0.f, 0.f, 0.f, 0.f);
            if (n4 < C2) v = *(const float4*)(B + (size_t)(k0 + kr) * C2 + n4);
            Bs[kr][n4 + 0] = v.x;
            Bs[kr][n4 + 1] = v.y;
            Bs[kr][n4 + 2] = v.z;
            Bs[kr][n4 + 3] = v.w;
        }
        __syncthreads();
        #pragma unroll
        for (int kk = 0; kk < 16; kk++) {
            float4 a = *(const float4*)&As[kk][ty * 4];
            float4 b = *(const float4*)&Bs[kk][tx * 4];
            float av[4] = {a.x, a.y, a.z, a.w};
            float bv[4] = {b.x, b.y, b.z, b.w};
            #pragma unroll
            for (int i = 0; i < 4; i++)
                #pragma unroll
                for (int j = 0; j < 4; j++) acc[i][j] += av[i] * bv[j];
        }
        __syncthreads();
    }
    #pragma unroll
    for (int i = 0; i < 4; i++) {
        int m = m0 + ty * 4 + i;
        if (m < NN && tx * 4 < C2) {
            float4 v = make_float4(acc[i][0], acc[i][1], acc[i][2], acc[i][3]);
            *(float4*)(g_h2 + (size_t)m * C2 + tx * 4) = v;
            Cs[ty * 4 + i][tx * 4 + 0] = acc[i][0];
            Cs[ty * 4 + i][tx * 4 + 1] = acc[i][1];
            Cs[ty * 4 + i][tx * 4 + 2] = acc[i][2];
            Cs[ty * 4 + i][tx * 4 + 3] = acc[i][3];
        }
    }
    __syncthreads();
    if (tid < 64 && m0 + tid < NN) {
        float s = 0.f, d = 0.f;
        #pragma unroll
        for (int c = 0; c < C2; c++) {
            float v = Cs[tid][c];
            s += v * att_s[c];
            d += v * att_d[c];
        }
        g_as2[m0 + tid] = s;
        g_ad2[m0 + tid] = d;
    }
}

__device__ __forceinline__ float lrelu(float e) { return e > 0.f ? e : 0.2f * e; }

// -------- layer 1 attention: warp/node, float2 lanes, 1 expf/lane ----------
__global__ void k_attn1(const float* __restrict__ b1) {
    int warp = threadIdx.x >> 5, lane = threadIdx.x & 31;
    int n = blockIdx.x * 8 + warp;
    if (n >= NN) return;
    int beg = g_off[n], end = g_off[n + 1];

    const int ha = lane >> 2;                 // head (8 heads x 4 lanes)
    const int c0 = 2 * lane;                  // channels {c0, c0+1}
    float ad = g_ad1[(size_t)n * 8 + ha];
    float ax = 0.f, ay = 0.f, dn = 0.f;
    int i = beg;
    for (; i + 1 < end; i += 2) {
        int s0 = g_csr_src[i], s1 = g_csr_src[i + 1];
        float w0 = __expf(lrelu(g_as1[(size_t)s0 * 8 + ha] + ad));
        float w1 = __expf(lrelu(g_as1[(size_t)s1 * 8 + ha] + ad));
        float2 h0 = *(const float2*)(g_h1 + (size_t)s0 * F1 + c0);
        float2 h1 = *(const float2*)(g_h1 + (size_t)s1 * F1 + c0);
        ax += w0 * h0.x + w1 * h1.x;
        ay += w0 * h0.y + w1 * h1.y;
        dn += w0 + w1;
    }
    if (i < end) {
        int s = g_csr_src[i];
        float w = __expf(lrelu(g_as1[(size_t)s * 8 + ha] + ad));
        float2 h = *(const float2*)(g_h1 + (size_t)s * F1 + c0);
        ax += w * h.x;
        ay += w * h.y;
        dn += w;
    }
    float inv = 1.f / dn;
    float2 o;
    o.x = fmaxf(ax * inv + b1[c0], 0.f);
    o.y = fmaxf(ay * inv + b1[c0 + 1], 0.f);
    *(float2*)(g_x1 + (size_t)n * F1 + c0) = o;
}

// -------- layer 2 attention + log_softmax: warp/node, float2 lanes ----------
__global__ void k_attn2(const float* __restrict__ b2, float* __restrict__ out) {
    int warp = threadIdx.x >> 5, lane = threadIdx.x & 31;
    int n = blockIdx.x * 8 + warp;
    if (n >= NN) return;
    int beg = g_off[n], end = g_off[n + 1];
    float ad = g_ad2[n];

    float ax = 0.f, ay = 0.f, dn = 0.f;
    int i = beg;
    for (; i + 1 < end; i += 2) {
        int s0 = g_csr_src[i], s1 = g_csr_src[i + 1];
        float w0 = __expf(lrelu(g_as2[s0] + ad));
        float w1 = __expf(lrelu(g_as2[s1] + ad));
        if (lane < 20) {
            float2 h0 = *(const float2*)(g_h2 + (size_t)s0 * C2 + 2 * lane);
            float2 h1 = *(const float2*)(g_h2 + (size_t)s1 * C2 + 2 * lane);
            ax += w0 * h0.x + w1 * h1.x;
            ay += w0 * h0.y + w1 * h1.y;
        }
        dn += w0 + w1;
    }
    if (i < end) {
        int s = g_csr_src[i];
        float w = __expf(lrelu(g_as2[s] + ad));
        if (lane < 20) {
            float2 h = *(const float2*)(g_h2 + (size_t)s * C2 + 2 * lane);
            ax += w * h.x;
            ay += w * h.y;
        }
        dn += w;
    }
    float inv = 1.f / dn;

    float v0 = (lane < 20) ? (ax * inv + b2[2 * lane]) : -1e30f;
    float v1 = (lane < 20) ? (ay * inv + b2[2 * lane + 1]) : -1e30f;
    float m = fmaxf(v0, v1);
    #pragma unroll
    for (int o = 16; o > 0; o >>= 1) m = fmaxf(m, __shfl_xor_sync(0xffffffffu, m, o));
    float se = (lane < 20) ? (__expf(v0 - m) + __expf(v1 - m)) : 0.f;
    #pragma unroll
    for (int o = 16; o > 0; o >>= 1) se += __shfl_xor_sync(0xffffffffu, se, o);
    float ls = m + logf(se);

    if (lane < 20) {
        float2 ov = make_float2(v0 - ls, v1 - ls);
        *(float2*)(out + (size_t)n * C2 + 2 * lane) = ov;
    }
}

// ---------------- launch (fork/join two-stream overlap) ----------------
extern "C" void kernel_launch(void* const* d_in, const int* in_sizes, int n_in,
                              void* d_out, int out_size) {
    const float* x   = (const float*)d_in[0];
    const int*   ei  = (const int*)d_in[1];
    const float* W1  = (const float*)d_in[2];
    const float* as1 = (const float*)d_in[3];
    const float* ad1 = (const float*)d_in[4];
    const float* b1  = (const float*)d_in[5];
    const float* W2  = (const float*)d_in[6];
    const float* as2 = (const float*)d_in[7];
    const float* ad2 = (const float*)d_in[8];
    const float* b2  = (const float*)d_in[9];
    float*       out = (float*)d_out;

    static cudaStream_t sB = nullptr;
    static cudaEvent_t eFork = nullptr, eJoin = nullptr;
    if (sB == nullptr) {
        cudaStreamCreateWithFlags(&sB, cudaStreamNonBlocking);
        cudaEventCreateWithFlags(&eFork, cudaEventDisableTiming);
        cudaEventCreateWithFlags(&eJoin, cudaEventDisableTiming);
    }

    // fork: branch B does W1 prep + GEMM1 (independent of CSR build)
    cudaEventRecord(eFork, 0);
    cudaStreamWaitEvent(sB, eFork, 0);
    k_prep<<<(F1 * KP2 + 255) / 256, 256, 0, sB>>>(W1);
    k_gemm1_mma<<<(NN + BM - 1) / BM, 256, 0, sB>>>(x, as1, ad1);
    cudaEventRecord(eJoin, sB);

    // branch A (capture stream): CSR build
    k_init<<<(NN + 255) / 256, 256>>>(ei);
    k_edges<<<(E_TOT + 255) / 256, 256>>>(ei);
    k_scan1<<<NB_SCAN, 256>>>();
    k_scan2<<<1, 256>>>();
    k_scan3<<<NB_SCAN, 256>>>();
    k_fill<<<(E_TOT + 255) / 256, 256>>>();

    // join, then the dependent tail
    cudaStreamWaitEvent(0, eJoin, 0);
    k_attn1<<<(NN + 7) / 8, 256>>>(b1);
    k_gemm2<<<(NN + 63) / 64, 256>>>(W2, as2, ad2);
    k_attn2<<<(NN + 7) / 8, 256>>>(b2, out);
}